// round 8
// baseline (speedup 1.0000x reference)
#include <cuda_runtime.h>
#include <math.h>

#define H      64
#define NFINE  (1 << 20)          // fine grid intervals over [0,1]
#define NC     (1 << 11)          // coarse grid intervals
#define NCTOT  (NC + 3)           // coarse entries: x = (idx-1)/NC
#define RSH    9                  // log2(NFINE/NC)
#define RMASK  ((1 << RSH) - 1)
#define KBUCK  (1 << 19)          // inverse-index buckets (8 MB of 16B entries)
#define MONO   1e-3f

__device__ float g_w2t[H * H];    // g_w2t[i*64+j] = exp(pw2[j][i])  (transposed)
__device__ float g_w1[H], g_b1[H], g_b2[H], g_w3[H], g_b3s;
__device__ float g_Ac[NCTOT];     // raw A at coarse grid (+/-1 pad): 8 KB, L1-resident
__device__ uint4 g_C[KBUCK];      // {J[k], T[J+1], T[J+2], T[J+3]} (floats as bits)

__device__ __forceinline__ float sigmoidf(float x) {
    return 1.0f / (1.0f + expf(-x));
}

// ---------------------------------------------------------------------------
// Kernel 0: one-shot weight prep -- exponentiate positivity-constrained
// weights, transpose w2 into global.
// ---------------------------------------------------------------------------
__global__ void prep_kernel(const float* __restrict__ pw1, const float* __restrict__ b1,
                            const float* __restrict__ pw2, const float* __restrict__ b2,
                            const float* __restrict__ pw3, const float* __restrict__ b3) {
    int e = blockIdx.x * blockDim.x + threadIdx.x;
    if (e < H * H) {
        int j = e >> 6, i = e & 63;
        g_w2t[i * H + j] = expf(pw2[e]);
    }
    if (e < H) {
        g_w1[e] = expf(pw1[e]);
        g_b1[e] = b1[e];
        g_b2[e] = b2[e];
        g_w3[e] = expf(pw3[e]);
    }
    if (e == 0) g_b3s = b3[0];
}

// ---------------------------------------------------------------------------
// Kernel 1: exact network eval A(x) on the coarse grid, ONE WARP PER POINT.
// ---------------------------------------------------------------------------
__global__ void coarse_kernel() {
    int gwarp = (blockIdx.x * blockDim.x + threadIdx.x) >> 5;
    int lane  = threadIdx.x & 31;
    if (gwarp >= NCTOT) return;
    float x = (float)(gwarp - 1) * (1.0f / (float)NC);

    float h1a = sigmoidf(fmaf(__ldg(&g_w1[lane]),      x, __ldg(&g_b1[lane])));
    float h1b = sigmoidf(fmaf(__ldg(&g_w1[lane + 32]), x, __ldg(&g_b1[lane + 32])));

    float acc0 = __ldg(&g_b2[2 * lane]);
    float acc1 = __ldg(&g_b2[2 * lane + 1]);
#pragma unroll
    for (int i = 0; i < 32; i++) {
        float  hv = __shfl_sync(0xffffffffu, h1a, i);
        float2 w  = __ldg(reinterpret_cast<const float2*>(&g_w2t[i * H + 2 * lane]));
        acc0 = fmaf(w.x, hv, acc0);
        acc1 = fmaf(w.y, hv, acc1);
    }
#pragma unroll
    for (int i = 0; i < 32; i++) {
        float  hv = __shfl_sync(0xffffffffu, h1b, i);
        float2 w  = __ldg(reinterpret_cast<const float2*>(&g_w2t[(i + 32) * H + 2 * lane]));
        acc0 = fmaf(w.x, hv, acc0);
        acc1 = fmaf(w.y, hv, acc1);
    }
    float part = fmaf(sigmoidf(acc0), __ldg(&g_w3[2 * lane]),
                      sigmoidf(acc1) * __ldg(&g_w3[2 * lane + 1]));
#pragma unroll
    for (int o = 16; o; o >>= 1) part += __shfl_xor_sync(0xffffffffu, part, o);

    if (lane == 0) g_Ac[gwarp] = sigmoidf(part + g_b3s) + MONO * x;
}

// ---------------------------------------------------------------------------
// Catmull-Rom interpolation of A at fine index j (error O(h^4), far below
// fp32 rounding of A itself). Coarse points take the exact value.
// Deterministic: identical fp32 ops wherever it is called, so table build
// and search fallback agree bit-for-bit.
// ---------------------------------------------------------------------------
__device__ __forceinline__ float evalA(int j) {
    int ci = j >> RSH;
    int f  = j & RMASK;
    if (f == 0) return __ldg(&g_Ac[ci + 1]);
    float t  = (float)f * (1.0f / (float)(1 << RSH));
    float P0 = __ldg(&g_Ac[ci]);
    float P1 = __ldg(&g_Ac[ci + 1]);
    float P2 = __ldg(&g_Ac[ci + 2]);
    float P3 = __ldg(&g_Ac[ci + 3]);
    float c1 = 0.5f * (P2 - P0);
    float c2 = P0 - 2.5f * P1 + 2.0f * P2 - 0.5f * P3;
    float c3 = 1.5f * (P1 - P2) + 0.5f * (P3 - P0);
    return P1 + t * (c1 + t * (c2 + t * c3));
}

// normalized fine-grid CDF value; same expression everywhere (bit-exact)
__device__ __forceinline__ float evalT(int j, float a0, float inv_den) {
    return (j == NFINE) ? 1.0f : (evalA(j) - a0) * inv_den;
}

// ---------------------------------------------------------------------------
// Kernel 2: fat packed inverse index ONLY (no T array stored at all; the
// search fallback recomputes T on the fly from the L1-resident 8 KB coarse
// table with identical arithmetic). Thread handles 4 fine points j..j+3:
// evaluates T at j..j+6 (shared endpoints use identical arithmetic in every
// thread, so bucket runs tile exactly) and writes
// g_C[k] = {j, T[j+1], T[j+2], T[j+3]} for k in [ceil(T[j]*K), ceil(T[j+1]*K)).
// ---------------------------------------------------------------------------
__global__ void table_kernel() {
    int jb = (blockIdx.x * blockDim.x + threadIdx.x) * 4;
    if (jb >= NFINE) return;
    const float a0      = g_Ac[1];        // A(0)
    const float a1      = g_Ac[1 + NC];   // A(1)
    const float inv_den = 1.0f / (a1 - a0);

    float tv[7];
#pragma unroll
    for (int m = 0; m < 7; m++) {
        int j = jb + m;
        tv[m] = (j <= NFINE) ? evalT(j, a0, inv_den)   // j==0 -> exact 0.0f
                             : 2.0f;                   // sentinel > any z
    }

#pragma unroll
    for (int m = 0; m < 4; m++) {
        int k0 = (int)ceilf(tv[m]     * (float)KBUCK);   // exact: pow2 scale
        int k1 = (int)ceilf(fminf(tv[m + 1], 1.0f) * (float)KBUCK);
        if (k0 < 0) k0 = 0;
        if (k1 > KBUCK) k1 = KBUCK;
        uint4 val = make_uint4((unsigned)(jb + m),
                               __float_as_uint(tv[m + 1]),
                               __float_as_uint(tv[m + 2]),
                               __float_as_uint(tv[m + 3]));
        for (int k = k0; k < k1; k++) g_C[k] = val;
    }
}

// ---------------------------------------------------------------------------
// Kernel 3: per-target inversion, 2 targets/thread (max warp count, no wave
// quantization). ONE aligned 16B gather (single 32B sector) resolves bracket
// widths <= 3 (dominant at 2 avg points/bucket); wider brackets load C[k+1].x
// and bisect with on-the-fly T recomputation (L1-hit LDGs on the 8 KB coarse
// table -- cheaper than an L2 gather per step). Equivalent to the reference
// 20-step bisection: lo = max{j : T[j] <= z}, out = (lo+0.5)*2^-20.
// ---------------------------------------------------------------------------
__device__ __forceinline__ float invert_one(float zi, float a0, float inv_den) {
    int k = (int)(zi * (float)KBUCK);            // exact floor: pow2 scale
    k = min(max(k, 0), KBUCK - 1);
    uint4 c = __ldg(&g_C[k]);
    int   j  = (int)c.x;                         // T[j] <= k/K <= zi
    float t1 = __uint_as_float(c.y);
    float t2 = __uint_as_float(c.z);
    float t3 = __uint_as_float(c.w);
    int lo;
    if (zi < t1)      lo = j;
    else if (zi < t2) lo = j + 1;
    else if (zi < t3) lo = j + 2;
    else {
        lo = j + 3;                              // T[j+3] <= zi
        int hi = (k < KBUCK - 1)
                   ? ((int)__ldg(reinterpret_cast<const unsigned*>(&g_C[k + 1])) + 1)
                   : NFINE;                      // T[hi] > zi
        while (hi - lo > 1) {
            int mid = (lo + hi) >> 1;
            if (evalT(mid, a0, inv_den) <= zi) lo = mid; else hi = mid;
        }
    }
    return (float)(2 * lo + 1) * 0x1p-21f;       // (lo + hi)/2 * 2^-20, exact
}

__global__ void search_kernel(const float* __restrict__ z, float* __restrict__ out, int n) {
    const float a0      = __ldg(&g_Ac[1]);
    const float a1      = __ldg(&g_Ac[1 + NC]);
    const float inv_den = 1.0f / (a1 - a0);
    int i = (blockIdx.x * blockDim.x + threadIdx.x) * 2;
    if (i + 1 < n) {
        float2 zv = *reinterpret_cast<const float2*>(z + i);
        float2 ov;
        ov.x = invert_one(zv.x, a0, inv_den);
        ov.y = invert_one(zv.y, a0, inv_den);
        *reinterpret_cast<float2*>(out + i) = ov;
    } else if (i < n) {
        out[i] = invert_one(z[i], a0, inv_den);
    }
}

// ---------------------------------------------------------------------------
extern "C" void kernel_launch(void* const* d_in, const int* in_sizes, int n_in,
                              void* d_out, int out_size) {
    const float* z   = (const float*)d_in[0];
    const float* pw1 = (const float*)d_in[1];
    const float* b1  = (const float*)d_in[2];
    const float* pw2 = (const float*)d_in[3];
    const float* b2  = (const float*)d_in[4];
    const float* pw3 = (const float*)d_in[5];
    const float* b3  = (const float*)d_in[6];
    float* out = (float*)d_out;
    int n = in_sizes[0];

    prep_kernel<<<(H * H + 255) / 256, 256>>>(pw1, b1, pw2, b2, pw3, b3);
    coarse_kernel<<<(NCTOT * 32 + 255) / 256, 256>>>();
    table_kernel<<<(NFINE / 4 + 255) / 256, 256>>>();
    int nq = (n + 1) / 2;
    search_kernel<<<(nq + 255) / 256, 256>>>(z, out, n);
}

// round 9
// speedup vs baseline: 1.1282x; 1.1282x over previous
#include <cuda_runtime.h>
#include <math.h>

#define H      64
#define NFINE  (1 << 20)          // fine grid intervals over [0,1]
#define NC     (1 << 11)          // coarse grid intervals
#define NCTOT  (NC + 3)           // coarse entries: x = (idx-1)/NC
#define RSH    9                  // log2(NFINE/NC)
#define RMASK  ((1 << RSH) - 1)
#define KBUCK  (1 << 19)          // inverse-index buckets (8 MB of 16B entries)
#define MONO   1e-3f

__device__ float g_w2t[H * H];    // g_w2t[i*64+j] = exp(pw2[j][i])  (transposed)
__device__ float g_w1[H], g_b1[H], g_b2[H], g_w3[H], g_b3s;
__device__ float g_Ac[NCTOT];     // raw A at coarse grid (+/-1 pad): 8 KB
__device__ float4 g_CF[NC];       // normalized Catmull-Rom coeffs per coarse cell: 32 KB
__device__ uint4 g_C[KBUCK];      // {J[k], T[J+1], T[J+2], T[J+3]} (floats as bits)

__device__ __forceinline__ float sigmoidf(float x) {
    return 1.0f / (1.0f + expf(-x));
}

// ---------------------------------------------------------------------------
// Kernel 0: one-shot weight prep -- exponentiate positivity-constrained
// weights, transpose w2 into global.
// ---------------------------------------------------------------------------
__global__ void prep_kernel(const float* __restrict__ pw1, const float* __restrict__ b1,
                            const float* __restrict__ pw2, const float* __restrict__ b2,
                            const float* __restrict__ pw3, const float* __restrict__ b3) {
    int e = blockIdx.x * blockDim.x + threadIdx.x;
    if (e < H * H) {
        int j = e >> 6, i = e & 63;
        g_w2t[i * H + j] = expf(pw2[e]);
    }
    if (e < H) {
        g_w1[e] = expf(pw1[e]);
        g_b1[e] = b1[e];
        g_b2[e] = b2[e];
        g_w3[e] = expf(pw3[e]);
    }
    if (e == 0) g_b3s = b3[0];
}

// ---------------------------------------------------------------------------
// Kernel 1: exact network eval A(x) on the coarse grid, ONE WARP PER POINT.
// ---------------------------------------------------------------------------
__global__ void coarse_kernel() {
    int gwarp = (blockIdx.x * blockDim.x + threadIdx.x) >> 5;
    int lane  = threadIdx.x & 31;
    if (gwarp >= NCTOT) return;
    float x = (float)(gwarp - 1) * (1.0f / (float)NC);

    float h1a = sigmoidf(fmaf(__ldg(&g_w1[lane]),      x, __ldg(&g_b1[lane])));
    float h1b = sigmoidf(fmaf(__ldg(&g_w1[lane + 32]), x, __ldg(&g_b1[lane + 32])));

    float acc0 = __ldg(&g_b2[2 * lane]);
    float acc1 = __ldg(&g_b2[2 * lane + 1]);
#pragma unroll
    for (int i = 0; i < 32; i++) {
        float  hv = __shfl_sync(0xffffffffu, h1a, i);
        float2 w  = __ldg(reinterpret_cast<const float2*>(&g_w2t[i * H + 2 * lane]));
        acc0 = fmaf(w.x, hv, acc0);
        acc1 = fmaf(w.y, hv, acc1);
    }
#pragma unroll
    for (int i = 0; i < 32; i++) {
        float  hv = __shfl_sync(0xffffffffu, h1b, i);
        float2 w  = __ldg(reinterpret_cast<const float2*>(&g_w2t[(i + 32) * H + 2 * lane]));
        acc0 = fmaf(w.x, hv, acc0);
        acc1 = fmaf(w.y, hv, acc1);
    }
    float part = fmaf(sigmoidf(acc0), __ldg(&g_w3[2 * lane]),
                      sigmoidf(acc1) * __ldg(&g_w3[2 * lane + 1]));
#pragma unroll
    for (int o = 16; o; o >>= 1) part += __shfl_xor_sync(0xffffffffu, part, o);

    if (lane == 0) g_Ac[gwarp] = sigmoidf(part + g_b3s) + MONO * x;
}

// ---------------------------------------------------------------------------
// Kernel 1b: pre-normalized Catmull-Rom coefficients per coarse cell.
// T(ci, t) = nP1 + t*(nc1 + t*(nc2 + t*nc3)),  t = (j & RMASK)/2^RSH.
// Cell 0 gives T(0)=0 exactly ((P1-a0)*inv_den with P1==a0).
// 32 KB total -> L1-resident during table build and search fallback.
// ---------------------------------------------------------------------------
__global__ void coeff_kernel() {
    int ci = blockIdx.x * blockDim.x + threadIdx.x;
    if (ci >= NC) return;
    const float a0      = g_Ac[1];
    const float a1      = g_Ac[1 + NC];
    const float inv_den = 1.0f / (a1 - a0);
    float P0 = g_Ac[ci];
    float P1 = g_Ac[ci + 1];
    float P2 = g_Ac[ci + 2];
    float P3 = g_Ac[ci + 3];
    float c1 = 0.5f * (P2 - P0);
    float c2 = P0 - 2.5f * P1 + 2.0f * P2 - 0.5f * P3;
    float c3 = 1.5f * (P1 - P2) + 0.5f * (P3 - P0);
    g_CF[ci] = make_float4((P1 - a0) * inv_den, c1 * inv_den,
                           c2 * inv_den, c3 * inv_den);
}

// normalized fine-grid CDF value: ONE LDG.128 + 3 FMA. Identical expression
// everywhere it is called, so table build and search fallback agree
// bit-for-bit (bracketing invariants hold exactly).
__device__ __forceinline__ float evalT(int j) {
    if (j >= NFINE) return 1.0f;
    float4 cf = __ldg(&g_CF[j >> RSH]);
    float  t  = (float)(j & RMASK) * (1.0f / (float)(1 << RSH));
    return fmaf(t, fmaf(t, fmaf(t, cf.w, cf.z), cf.y), cf.x);
}

// ---------------------------------------------------------------------------
// Kernel 2: fat packed inverse index. Thread handles 4 fine points jb..jb+3:
// evaluates T at jb..jb+6 via the coeff table (7 L1-hit LDG.128, shared
// endpoints bit-identical across threads so bucket runs tile exactly) and
// writes g_C[k] = {j, T[j+1], T[j+2], T[j+3]} for
// k in [ceil(T[j]*K), ceil(T[j+1]*K)).
// ---------------------------------------------------------------------------
__global__ void table_kernel() {
    int jb = (blockIdx.x * blockDim.x + threadIdx.x) * 4;
    if (jb >= NFINE) return;

    float tv[7];
#pragma unroll
    for (int m = 0; m < 7; m++) {
        int j = jb + m;
        tv[m] = (j <= NFINE) ? evalT(j) : 2.0f;   // sentinel > any z
    }

#pragma unroll
    for (int m = 0; m < 4; m++) {
        int k0 = (int)ceilf(tv[m]     * (float)KBUCK);   // exact: pow2 scale
        int k1 = (int)ceilf(fminf(tv[m + 1], 1.0f) * (float)KBUCK);
        if (k0 < 0) k0 = 0;
        if (k1 > KBUCK) k1 = KBUCK;
        uint4 val = make_uint4((unsigned)(jb + m),
                               __float_as_uint(tv[m + 1]),
                               __float_as_uint(tv[m + 2]),
                               __float_as_uint(tv[m + 3]));
        for (int k = k0; k < k1; k++) g_C[k] = val;
    }
}

// ---------------------------------------------------------------------------
// Kernel 3: per-target inversion, 4 targets/thread, sequential low-register
// form (proven best: R7). ONE aligned 16B gather (single 32B sector) resolves
// bracket widths <= 3 (dominant at 2 avg points/bucket); wider brackets load
// C[k+1].x and bisect with evalT on the 32 KB L1-resident coeff table
// (1 LDG.128 + 3 FMA per step). Equivalent to the reference 20-step
// bisection: lo = max{j : T[j] <= z}, out = (lo+0.5)*2^-20.
// ---------------------------------------------------------------------------
__device__ __forceinline__ float invert_one(float zi) {
    int k = (int)(zi * (float)KBUCK);            // exact floor: pow2 scale
    k = min(max(k, 0), KBUCK - 1);
    uint4 c = __ldg(&g_C[k]);
    int   j  = (int)c.x;                         // T[j] <= k/K <= zi
    float t1 = __uint_as_float(c.y);
    float t2 = __uint_as_float(c.z);
    float t3 = __uint_as_float(c.w);
    int lo;
    if (zi < t1)      lo = j;
    else if (zi < t2) lo = j + 1;
    else if (zi < t3) lo = j + 2;
    else {
        lo = j + 3;                              // T[j+3] <= zi
        int hi = (k < KBUCK - 1)
                   ? ((int)__ldg(reinterpret_cast<const unsigned*>(&g_C[k + 1])) + 1)
                   : NFINE;                      // T[hi] > zi
        while (hi - lo > 1) {
            int mid = (lo + hi) >> 1;
            if (evalT(mid) <= zi) lo = mid; else hi = mid;
        }
    }
    return (float)(2 * lo + 1) * 0x1p-21f;       // (lo + hi)/2 * 2^-20, exact
}

__global__ void search_kernel(const float* __restrict__ z, float* __restrict__ out, int n) {
    int i = (blockIdx.x * blockDim.x + threadIdx.x) * 4;
    if (i + 3 < n) {
        float4 zv = *reinterpret_cast<const float4*>(z + i);
        float4 ov;
        ov.x = invert_one(zv.x);
        ov.y = invert_one(zv.y);
        ov.z = invert_one(zv.z);
        ov.w = invert_one(zv.w);
        *reinterpret_cast<float4*>(out + i) = ov;
    } else {
        for (; i < n; i++) out[i] = invert_one(z[i]);
    }
}

// ---------------------------------------------------------------------------
extern "C" void kernel_launch(void* const* d_in, const int* in_sizes, int n_in,
                              void* d_out, int out_size) {
    const float* z   = (const float*)d_in[0];
    const float* pw1 = (const float*)d_in[1];
    const float* b1  = (const float*)d_in[2];
    const float* pw2 = (const float*)d_in[3];
    const float* b2  = (const float*)d_in[4];
    const float* pw3 = (const float*)d_in[5];
    const float* b3  = (const float*)d_in[6];
    float* out = (float*)d_out;
    int n = in_sizes[0];

    prep_kernel<<<(H * H + 255) / 256, 256>>>(pw1, b1, pw2, b2, pw3, b3);
    coarse_kernel<<<(NCTOT * 32 + 255) / 256, 256>>>();
    coeff_kernel<<<(NC + 255) / 256, 256>>>();
    table_kernel<<<(NFINE / 4 + 255) / 256, 256>>>();
    int nq = (n + 3) / 4;
    search_kernel<<<(nq + 255) / 256, 256>>>(z, out, n);
}

// round 10
// speedup vs baseline: 1.2347x; 1.0943x over previous
#include <cuda_runtime.h>
#include <math.h>

#define H      64
#define NFINE  (1 << 20)          // fine grid intervals over [0,1]
#define NC     (1 << 11)          // coarse grid intervals
#define NCTOT  (NC + 3)           // coarse entries: x = (idx-1)/NC
#define RSH    9                  // log2(NFINE/NC)
#define RMASK  ((1 << RSH) - 1)
#define KBUCK  (1 << 19)          // inverse-index buckets (8 MB of 16B entries)
#define MONO   1e-3f

__device__ float g_w2t[H * H];    // g_w2t[i*64+j] = exp(pw2[j][i])  (transposed)
__device__ float g_w1[H], g_b1[H], g_b2[H], g_w3[H], g_b3s;
__device__ float g_Ac[NCTOT];     // raw A at coarse grid (+/-1 pad): 8 KB
__device__ float4 g_CF[NC];       // normalized Catmull-Rom coeffs per cell: 32 KB
__device__ uint4 g_C[KBUCK];      // {J[k], T[J+1], T[J+2], T[J+3]} (floats as bits)

__device__ __forceinline__ float sigmoidf(float x) {
    return 1.0f / (1.0f + expf(-x));
}

// ---------------------------------------------------------------------------
// Kernel 0: one-shot weight prep -- exponentiate positivity-constrained
// weights, transpose w2 into global.
// ---------------------------------------------------------------------------
__global__ void prep_kernel(const float* __restrict__ pw1, const float* __restrict__ b1,
                            const float* __restrict__ pw2, const float* __restrict__ b2,
                            const float* __restrict__ pw3, const float* __restrict__ b3) {
    int e = blockIdx.x * blockDim.x + threadIdx.x;
    if (e < H * H) {
        int j = e >> 6, i = e & 63;
        g_w2t[i * H + j] = expf(pw2[e]);
    }
    if (e < H) {
        g_w1[e] = expf(pw1[e]);
        g_b1[e] = b1[e];
        g_b2[e] = b2[e];
        g_w3[e] = expf(pw3[e]);
    }
    if (e == 0) g_b3s = b3[0];
}

// ---------------------------------------------------------------------------
// Kernel 1: exact network eval A(x) on the coarse grid, ONE WARP PER POINT.
// ---------------------------------------------------------------------------
__global__ void coarse_kernel() {
    int gwarp = (blockIdx.x * blockDim.x + threadIdx.x) >> 5;
    int lane  = threadIdx.x & 31;
    if (gwarp >= NCTOT) return;
    float x = (float)(gwarp - 1) * (1.0f / (float)NC);

    float h1a = sigmoidf(fmaf(__ldg(&g_w1[lane]),      x, __ldg(&g_b1[lane])));
    float h1b = sigmoidf(fmaf(__ldg(&g_w1[lane + 32]), x, __ldg(&g_b1[lane + 32])));

    float acc0 = __ldg(&g_b2[2 * lane]);
    float acc1 = __ldg(&g_b2[2 * lane + 1]);
#pragma unroll
    for (int i = 0; i < 32; i++) {
        float  hv = __shfl_sync(0xffffffffu, h1a, i);
        float2 w  = __ldg(reinterpret_cast<const float2*>(&g_w2t[i * H + 2 * lane]));
        acc0 = fmaf(w.x, hv, acc0);
        acc1 = fmaf(w.y, hv, acc1);
    }
#pragma unroll
    for (int i = 0; i < 32; i++) {
        float  hv = __shfl_sync(0xffffffffu, h1b, i);
        float2 w  = __ldg(reinterpret_cast<const float2*>(&g_w2t[(i + 32) * H + 2 * lane]));
        acc0 = fmaf(w.x, hv, acc0);
        acc1 = fmaf(w.y, hv, acc1);
    }
    float part = fmaf(sigmoidf(acc0), __ldg(&g_w3[2 * lane]),
                      sigmoidf(acc1) * __ldg(&g_w3[2 * lane + 1]));
#pragma unroll
    for (int o = 16; o; o >>= 1) part += __shfl_xor_sync(0xffffffffu, part, o);

    if (lane == 0) g_Ac[gwarp] = sigmoidf(part + g_b3s) + MONO * x;
}

// normalized Catmull-Rom coefficients for one cell from P0..P3 (the SAME
// formula everywhere -> bit-identical results wherever computed)
__device__ __forceinline__ float4 make_coeffs(float P0, float P1, float P2, float P3,
                                              float a0, float inv_den) {
    float c1 = 0.5f * (P2 - P0);
    float c2 = P0 - 2.5f * P1 + 2.0f * P2 - 0.5f * P3;
    float c3 = 1.5f * (P1 - P2) + 0.5f * (P3 - P0);
    return make_float4((P1 - a0) * inv_den, c1 * inv_den, c2 * inv_den, c3 * inv_den);
}

__device__ __forceinline__ float horner(float4 cf, int f) {
    float t = (float)f * (1.0f / (float)(1 << RSH));
    return fmaf(t, fmaf(t, fmaf(t, cf.w, cf.z), cf.y), cf.x);
}

// ---------------------------------------------------------------------------
// Kernel 2 (fused coeff+table): thread handles 8 fine points jb..jb+7. The
// 11 T-evals needed (run bounds jb..jb+8, payload to jb+10) span at most 2
// coarse cells; load g_Ac[ci..ci+4] once (5 scalar L1-hit loads), build both
// cells' normalized coeff sets in registers, then every eval is 3 FMA.
// The cell-head thread (jb & 511 == 0) stores its coeffs to g_CF -- the
// exact bits it used -- so the search fallback (which loads g_CF) agrees
// bit-for-bit. Writes g_C[k] = {j, T[j+1], T[j+2], T[j+3]} for
// k in [ceil(T[j]*K), ceil(T[j+1]*K)).
// ---------------------------------------------------------------------------
__global__ void table_kernel() {
    int jb = (blockIdx.x * blockDim.x + threadIdx.x) * 8;
    if (jb >= NFINE) return;
    const float a0      = __ldg(&g_Ac[1]);        // A(0)
    const float a1      = __ldg(&g_Ac[1 + NC]);   // A(1)
    const float inv_den = 1.0f / (a1 - a0);

    int ci = jb >> RSH;
    float P0 = __ldg(&g_Ac[ci]);
    float P1 = __ldg(&g_Ac[ci + 1]);
    float P2 = __ldg(&g_Ac[ci + 2]);
    float P3 = __ldg(&g_Ac[ci + 3]);
    // guard: ci+4 <= NCTOT-1 always needed only when second cell is real
    float P4 = (ci + 4 < NCTOT) ? __ldg(&g_Ac[ci + 4]) : 0.0f;

    float4 cfa = make_coeffs(P0, P1, P2, P3, a0, inv_den);   // cell ci
    float4 cfb = make_coeffs(P1, P2, P3, P4, a0, inv_den);   // cell ci+1

    if ((jb & RMASK) == 0) g_CF[ci] = cfa;       // cell head publishes coeffs

    float tv[11];
#pragma unroll
    for (int m = 0; m < 11; m++) {
        int j = jb + m;
        if (j < NFINE) {
            int f = j & RMASK;
            // j is in cell ci except when it wrapped to ci+1
            tv[m] = ((j >> RSH) == ci) ? horner(cfa, f) : horner(cfb, f);
        } else {
            tv[m] = (j == NFINE) ? 1.0f : 2.0f;  // top pin / sentinel > any z
        }
    }

#pragma unroll
    for (int m = 0; m < 8; m++) {
        int k0 = (int)ceilf(tv[m]     * (float)KBUCK);   // exact: pow2 scale
        int k1 = (int)ceilf(fminf(tv[m + 1], 1.0f) * (float)KBUCK);
        if (k0 < 0) k0 = 0;
        if (k1 > KBUCK) k1 = KBUCK;
        uint4 val = make_uint4((unsigned)(jb + m),
                               __float_as_uint(tv[m + 1]),
                               __float_as_uint(tv[m + 2]),
                               __float_as_uint(tv[m + 3]));
        for (int k = k0; k < k1; k++) g_C[k] = val;
    }
}

// normalized fine-grid CDF value from the published coeff table (32 KB,
// L1-resident): ONE LDG.128 + 3 FMA. Bit-identical to table build.
__device__ __forceinline__ float evalT(int j) {
    if (j >= NFINE) return 1.0f;
    float4 cf = __ldg(&g_CF[j >> RSH]);
    return horner(cf, j & RMASK);
}

// ---------------------------------------------------------------------------
// Kernel 3: per-target inversion, 4 targets/thread, sequential low-register
// form (proven best). ONE aligned 16B gather -- via __ldcg so the 8 MB
// single-touch table does not evict the L1-resident CF table -- resolves
// bracket widths <= 3 (dominant at 2 avg points/bucket); wider brackets load
// C[k+1].x and bisect with evalT (1 L1 LDG.128 + 3 FMA per step).
// Equivalent to the reference 20-step bisection:
// lo = max{j : T[j] <= z}, out = (lo+0.5)*2^-20.
// ---------------------------------------------------------------------------
__device__ __forceinline__ float invert_one(float zi) {
    int k = (int)(zi * (float)KBUCK);            // exact floor: pow2 scale
    k = min(max(k, 0), KBUCK - 1);
    uint4 c = __ldcg(&g_C[k]);
    int   j  = (int)c.x;                         // T[j] <= k/K <= zi
    float t1 = __uint_as_float(c.y);
    float t2 = __uint_as_float(c.z);
    float t3 = __uint_as_float(c.w);
    int lo;
    if (zi < t1)      lo = j;
    else if (zi < t2) lo = j + 1;
    else if (zi < t3) lo = j + 2;
    else {
        lo = j + 3;                              // T[j+3] <= zi
        int hi = (k < KBUCK - 1)
                   ? ((int)__ldcg(reinterpret_cast<const unsigned*>(&g_C[k + 1])) + 1)
                   : NFINE;                      // T[hi] > zi
        while (hi - lo > 1) {
            int mid = (lo + hi) >> 1;
            if (evalT(mid) <= zi) lo = mid; else hi = mid;
        }
    }
    return (float)(2 * lo + 1) * 0x1p-21f;       // (lo + hi)/2 * 2^-20, exact
}

__global__ void search_kernel(const float* __restrict__ z, float* __restrict__ out, int n) {
    int i = (blockIdx.x * blockDim.x + threadIdx.x) * 4;
    if (i + 3 < n) {
        float4 zv = *reinterpret_cast<const float4*>(z + i);
        float4 ov;
        ov.x = invert_one(zv.x);
        ov.y = invert_one(zv.y);
        ov.z = invert_one(zv.z);
        ov.w = invert_one(zv.w);
        *reinterpret_cast<float4*>(out + i) = ov;
    } else {
        for (; i < n; i++) out[i] = invert_one(z[i]);
    }
}

// ---------------------------------------------------------------------------
extern "C" void kernel_launch(void* const* d_in, const int* in_sizes, int n_in,
                              void* d_out, int out_size) {
    const float* z   = (const float*)d_in[0];
    const float* pw1 = (const float*)d_in[1];
    const float* b1  = (const float*)d_in[2];
    const float* pw2 = (const float*)d_in[3];
    const float* b2  = (const float*)d_in[4];
    const float* pw3 = (const float*)d_in[5];
    const float* b3  = (const float*)d_in[6];
    float* out = (float*)d_out;
    int n = in_sizes[0];

    prep_kernel<<<(H * H + 255) / 256, 256>>>(pw1, b1, pw2, b2, pw3, b3);
    coarse_kernel<<<(NCTOT * 32 + 255) / 256, 256>>>();
    table_kernel<<<(NFINE / 8 + 255) / 256, 256>>>();
    int nq = (n + 3) / 4;
    search_kernel<<<(nq + 255) / 256, 256>>>(z, out, n);
}

// round 11
// speedup vs baseline: 1.2361x; 1.0012x over previous
#include <cuda_runtime.h>
#include <math.h>

#define H      64
#define NFINE  (1 << 20)          // fine grid intervals over [0,1]
#define NC     (1 << 11)          // coarse grid intervals
#define NCTOT  (NC + 3)           // coarse entries: x = (idx-1)/NC
#define RSH    9                  // log2(NFINE/NC)
#define RMASK  ((1 << RSH) - 1)
#define KBUCK  (1 << 19)          // inverse-index buckets (8 MB of 16B entries)
#define MONO   1e-3f

__device__ float g_w2t[H * H];    // g_w2t[i*64+j] = exp(pw2[j][i])  (transposed)
__device__ float g_w1[H], g_b1[H], g_b2[H], g_w3[H], g_b3s;
__device__ float g_Ac[NCTOT];     // raw A at coarse grid (+/-1 pad): 8 KB
__device__ float4 g_CF[NC];       // normalized Catmull-Rom coeffs per cell: 32 KB
__device__ uint4 g_C[KBUCK];      // {J[k], T[J+1], T[J+2], T[J+3]} (floats as bits)

__device__ __forceinline__ float sigmoidf(float x) {
    return 1.0f / (1.0f + expf(-x));
}

// ---------------------------------------------------------------------------
// Kernel 0: one-shot weight prep -- exponentiate positivity-constrained
// weights, transpose w2 into global.
// ---------------------------------------------------------------------------
__global__ void prep_kernel(const float* __restrict__ pw1, const float* __restrict__ b1,
                            const float* __restrict__ pw2, const float* __restrict__ b2,
                            const float* __restrict__ pw3, const float* __restrict__ b3) {
    int e = blockIdx.x * blockDim.x + threadIdx.x;
    if (e < H * H) {
        int j = e >> 6, i = e & 63;
        g_w2t[i * H + j] = expf(pw2[e]);
    }
    if (e < H) {
        g_w1[e] = expf(pw1[e]);
        g_b1[e] = b1[e];
        g_b2[e] = b2[e];
        g_w3[e] = expf(pw3[e]);
    }
    if (e == 0) g_b3s = b3[0];
}

// ---------------------------------------------------------------------------
// Kernel 1: exact network eval A(x) on the coarse grid, ONE WARP PER POINT.
// ---------------------------------------------------------------------------
__global__ void coarse_kernel() {
    int gwarp = (blockIdx.x * blockDim.x + threadIdx.x) >> 5;
    int lane  = threadIdx.x & 31;
    if (gwarp >= NCTOT) return;
    float x = (float)(gwarp - 1) * (1.0f / (float)NC);

    float h1a = sigmoidf(fmaf(__ldg(&g_w1[lane]),      x, __ldg(&g_b1[lane])));
    float h1b = sigmoidf(fmaf(__ldg(&g_w1[lane + 32]), x, __ldg(&g_b1[lane + 32])));

    float acc0 = __ldg(&g_b2[2 * lane]);
    float acc1 = __ldg(&g_b2[2 * lane + 1]);
#pragma unroll
    for (int i = 0; i < 32; i++) {
        float  hv = __shfl_sync(0xffffffffu, h1a, i);
        float2 w  = __ldg(reinterpret_cast<const float2*>(&g_w2t[i * H + 2 * lane]));
        acc0 = fmaf(w.x, hv, acc0);
        acc1 = fmaf(w.y, hv, acc1);
    }
#pragma unroll
    for (int i = 0; i < 32; i++) {
        float  hv = __shfl_sync(0xffffffffu, h1b, i);
        float2 w  = __ldg(reinterpret_cast<const float2*>(&g_w2t[(i + 32) * H + 2 * lane]));
        acc0 = fmaf(w.x, hv, acc0);
        acc1 = fmaf(w.y, hv, acc1);
    }
    float part = fmaf(sigmoidf(acc0), __ldg(&g_w3[2 * lane]),
                      sigmoidf(acc1) * __ldg(&g_w3[2 * lane + 1]));
#pragma unroll
    for (int o = 16; o; o >>= 1) part += __shfl_xor_sync(0xffffffffu, part, o);

    if (lane == 0) g_Ac[gwarp] = sigmoidf(part + g_b3s) + MONO * x;
}

// normalized Catmull-Rom coefficients for one cell from P0..P3 (the SAME
// formula everywhere -> bit-identical results wherever computed)
__device__ __forceinline__ float4 make_coeffs(float P0, float P1, float P2, float P3,
                                              float a0, float inv_den) {
    float c1 = 0.5f * (P2 - P0);
    float c2 = P0 - 2.5f * P1 + 2.0f * P2 - 0.5f * P3;
    float c3 = 1.5f * (P1 - P2) + 0.5f * (P3 - P0);
    return make_float4((P1 - a0) * inv_den, c1 * inv_den, c2 * inv_den, c3 * inv_den);
}

__device__ __forceinline__ float horner(float4 cf, int f) {
    float t = (float)f * (1.0f / (float)(1 << RSH));
    return fmaf(t, fmaf(t, fmaf(t, cf.w, cf.z), cf.y), cf.x);
}

// ---------------------------------------------------------------------------
// Kernel 2 (fused coeff+table): thread handles 8 fine points jb..jb+7. The
// 11 T-evals needed span at most 2 coarse cells; load g_Ac[ci..ci+4] once,
// build both cells' normalized coeff sets in registers, then every eval is
// 3 FMA. The cell-head thread publishes its coeffs to g_CF (exact bits it
// used) so the search fallback agrees bit-for-bit. Writes
// g_C[k] = {j, T[j+1], T[j+2], T[j+3]} for k in [ceil(T[j]*K), ceil(T[j+1]*K)).
// ---------------------------------------------------------------------------
__global__ void table_kernel() {
    int jb = (blockIdx.x * blockDim.x + threadIdx.x) * 8;
    if (jb >= NFINE) return;
    const float a0      = __ldg(&g_Ac[1]);        // A(0)
    const float a1      = __ldg(&g_Ac[1 + NC]);   // A(1)
    const float inv_den = 1.0f / (a1 - a0);

    int ci = jb >> RSH;
    float P0 = __ldg(&g_Ac[ci]);
    float P1 = __ldg(&g_Ac[ci + 1]);
    float P2 = __ldg(&g_Ac[ci + 2]);
    float P3 = __ldg(&g_Ac[ci + 3]);
    float P4 = (ci + 4 < NCTOT) ? __ldg(&g_Ac[ci + 4]) : 0.0f;

    float4 cfa = make_coeffs(P0, P1, P2, P3, a0, inv_den);   // cell ci
    float4 cfb = make_coeffs(P1, P2, P3, P4, a0, inv_den);   // cell ci+1

    if ((jb & RMASK) == 0) g_CF[ci] = cfa;       // cell head publishes coeffs

    float tv[11];
#pragma unroll
    for (int m = 0; m < 11; m++) {
        int j = jb + m;
        if (j < NFINE) {
            int f = j & RMASK;
            tv[m] = ((j >> RSH) == ci) ? horner(cfa, f) : horner(cfb, f);
        } else {
            tv[m] = (j == NFINE) ? 1.0f : 2.0f;  // top pin / sentinel > any z
        }
    }

#pragma unroll
    for (int m = 0; m < 8; m++) {
        int k0 = (int)ceilf(tv[m]     * (float)KBUCK);   // exact: pow2 scale
        int k1 = (int)ceilf(fminf(tv[m + 1], 1.0f) * (float)KBUCK);
        if (k0 < 0) k0 = 0;
        if (k1 > KBUCK) k1 = KBUCK;
        uint4 val = make_uint4((unsigned)(jb + m),
                               __float_as_uint(tv[m + 1]),
                               __float_as_uint(tv[m + 2]),
                               __float_as_uint(tv[m + 3]));
        for (int k = k0; k < k1; k++) g_C[k] = val;
    }
}

// normalized fine-grid CDF value from the published coeff table (32 KB,
// L1-resident): ONE LDG.128 + 3 FMA. Bit-identical to table build.
__device__ __forceinline__ float evalT(int j) {
    if (j >= NFINE) return 1.0f;
    float4 cf = __ldg(&g_CF[j >> RSH]);
    return horner(cf, j & RMASK);
}

// ---------------------------------------------------------------------------
// Kernel 3: per-target inversion, 2 targets/thread (3907 blocks = 3.3 waves
// of the 8-block/SM occupancy limit; kills the 1.65-wave quantization tail
// profiled in R10 while keeping the proven sequential low-register form).
// ONE aligned 16B __ldcg gather resolves bracket widths <= 3 (dominant);
// wider brackets load C[k+1].x and bisect with evalT (1 L1 LDG.128 + 3 FMA
// per step). Equivalent to the reference 20-step bisection:
// lo = max{j : T[j] <= z}, out = (lo+0.5)*2^-20.
// ---------------------------------------------------------------------------
__device__ __forceinline__ float invert_one(float zi) {
    int k = (int)(zi * (float)KBUCK);            // exact floor: pow2 scale
    k = min(max(k, 0), KBUCK - 1);
    uint4 c = __ldcg(&g_C[k]);
    int   j  = (int)c.x;                         // T[j] <= k/K <= zi
    float t1 = __uint_as_float(c.y);
    float t2 = __uint_as_float(c.z);
    float t3 = __uint_as_float(c.w);
    int lo;
    if (zi < t1)      lo = j;
    else if (zi < t2) lo = j + 1;
    else if (zi < t3) lo = j + 2;
    else {
        lo = j + 3;                              // T[j+3] <= zi
        int hi = (k < KBUCK - 1)
                   ? ((int)__ldcg(reinterpret_cast<const unsigned*>(&g_C[k + 1])) + 1)
                   : NFINE;                      // T[hi] > zi
        while (hi - lo > 1) {
            int mid = (lo + hi) >> 1;
            if (evalT(mid) <= zi) lo = mid; else hi = mid;
        }
    }
    return (float)(2 * lo + 1) * 0x1p-21f;       // (lo + hi)/2 * 2^-20, exact
}

__global__ void search_kernel(const float* __restrict__ z, float* __restrict__ out, int n) {
    int i = (blockIdx.x * blockDim.x + threadIdx.x) * 2;
    if (i + 1 < n) {
        float2 zv = *reinterpret_cast<const float2*>(z + i);
        float2 ov;
        ov.x = invert_one(zv.x);
        ov.y = invert_one(zv.y);
        *reinterpret_cast<float2*>(out + i) = ov;
    } else if (i < n) {
        out[i] = invert_one(z[i]);
    }
}

// ---------------------------------------------------------------------------
extern "C" void kernel_launch(void* const* d_in, const int* in_sizes, int n_in,
                              void* d_out, int out_size) {
    const float* z   = (const float*)d_in[0];
    const float* pw1 = (const float*)d_in[1];
    const float* b1  = (const float*)d_in[2];
    const float* pw2 = (const float*)d_in[3];
    const float* b2  = (const float*)d_in[4];
    const float* pw3 = (const float*)d_in[5];
    const float* b3  = (const float*)d_in[6];
    float* out = (float*)d_out;
    int n = in_sizes[0];

    prep_kernel<<<(H * H + 255) / 256, 256>>>(pw1, b1, pw2, b2, pw3, b3);
    coarse_kernel<<<(NCTOT * 32 + 255) / 256, 256>>>();
    table_kernel<<<(NFINE / 8 + 255) / 256, 256>>>();
    int nq = (n + 1) / 2;
    search_kernel<<<(nq + 255) / 256, 256>>>(z, out, n);
}

// round 12
// speedup vs baseline: 1.3372x; 1.0817x over previous
#include <cuda_runtime.h>
#include <math.h>

#define H      64
#define NFINE  (1 << 20)          // fine grid intervals over [0,1]
#define NC     (1 << 11)          // coarse grid intervals (= cubic cells)
#define NCTOT  (NC + 3)           // coarse entries: x = (idx-1)/NC
#define RSH    9                  // log2(NFINE/NC) = fine points per cell
#define ZSH    13                 // log2(z-bucket count)
#define ZB     (1 << ZSH)         // z buckets -> 16 KB uint16 map (L1-resident)
#define MONO   1e-3f

__device__ float g_w2t[H * H];    // g_w2t[i*64+j] = exp(pw2[j][i])  (transposed)
__device__ float g_w1[H], g_b1[H], g_b2[H], g_w3[H], g_b3s;
__device__ float g_Ac[NCTOT];     // raw A at coarse grid (+/-1 pad): 8 KB
__device__ float4 g_CF[NC];       // normalized Catmull-Rom coeffs per cell: 32 KB
__device__ float  g_TS[NC + 1];   // cell-start T values (== CF[c].x bits): 8 KB
__device__ unsigned short g_map[ZB]; // z-bucket -> max cell c with TS[c] <= k/ZB

__device__ __forceinline__ float sigmoidf(float x) {
    return 1.0f / (1.0f + expf(-x));
}

// ---------------------------------------------------------------------------
// Kernel 0: one-shot weight prep -- exponentiate positivity-constrained
// weights, transpose w2 into global.
// ---------------------------------------------------------------------------
__global__ void prep_kernel(const float* __restrict__ pw1, const float* __restrict__ b1,
                            const float* __restrict__ pw2, const float* __restrict__ b2,
                            const float* __restrict__ pw3, const float* __restrict__ b3) {
    int e = blockIdx.x * blockDim.x + threadIdx.x;
    if (e < H * H) {
        int j = e >> 6, i = e & 63;
        g_w2t[i * H + j] = expf(pw2[e]);
    }
    if (e < H) {
        g_w1[e] = expf(pw1[e]);
        g_b1[e] = b1[e];
        g_b2[e] = b2[e];
        g_w3[e] = expf(pw3[e]);
    }
    if (e == 0) g_b3s = b3[0];
}

// ---------------------------------------------------------------------------
// Kernel 1: exact network eval A(x) on the coarse grid, ONE WARP PER POINT.
// ---------------------------------------------------------------------------
__global__ void coarse_kernel() {
    int gwarp = (blockIdx.x * blockDim.x + threadIdx.x) >> 5;
    int lane  = threadIdx.x & 31;
    if (gwarp >= NCTOT) return;
    float x = (float)(gwarp - 1) * (1.0f / (float)NC);

    float h1a = sigmoidf(fmaf(__ldg(&g_w1[lane]),      x, __ldg(&g_b1[lane])));
    float h1b = sigmoidf(fmaf(__ldg(&g_w1[lane + 32]), x, __ldg(&g_b1[lane + 32])));

    float acc0 = __ldg(&g_b2[2 * lane]);
    float acc1 = __ldg(&g_b2[2 * lane + 1]);
#pragma unroll
    for (int i = 0; i < 32; i++) {
        float  hv = __shfl_sync(0xffffffffu, h1a, i);
        float2 w  = __ldg(reinterpret_cast<const float2*>(&g_w2t[i * H + 2 * lane]));
        acc0 = fmaf(w.x, hv, acc0);
        acc1 = fmaf(w.y, hv, acc1);
    }
#pragma unroll
    for (int i = 0; i < 32; i++) {
        float  hv = __shfl_sync(0xffffffffu, h1b, i);
        float2 w  = __ldg(reinterpret_cast<const float2*>(&g_w2t[(i + 32) * H + 2 * lane]));
        acc0 = fmaf(w.x, hv, acc0);
        acc1 = fmaf(w.y, hv, acc1);
    }
    float part = fmaf(sigmoidf(acc0), __ldg(&g_w3[2 * lane]),
                      sigmoidf(acc1) * __ldg(&g_w3[2 * lane + 1]));
#pragma unroll
    for (int o = 16; o; o >>= 1) part += __shfl_xor_sync(0xffffffffu, part, o);

    if (lane == 0) g_Ac[gwarp] = sigmoidf(part + g_b3s) + MONO * x;
}

// normalized Catmull-Rom coefficients for one cell from P0..P3 (the SAME
// formula everywhere -> bit-identical results wherever computed)
__device__ __forceinline__ float4 make_coeffs(float P0, float P1, float P2, float P3,
                                              float a0, float inv_den) {
    float c1 = 0.5f * (P2 - P0);
    float c2 = P0 - 2.5f * P1 + 2.0f * P2 - 0.5f * P3;
    float c3 = 1.5f * (P1 - P2) + 0.5f * (P3 - P0);
    return make_float4((P1 - a0) * inv_den, c1 * inv_den, c2 * inv_den, c3 * inv_den);
}

// T at fine offset f within a cell (t = f/512): bit-identical everywhere.
__device__ __forceinline__ float horner(float4 cf, int f) {
    float t = (float)f * (1.0f / (float)(1 << RSH));
    return fmaf(t, fmaf(t, fmaf(t, cf.w, cf.z), cf.y), cf.x);
}

// ---------------------------------------------------------------------------
// Kernel 2: per-cell coefficients + cell-start values + z-bucket cell map.
// TS is monotone in fp32 (A gains >= MONO/NC ~ 4.9e-7 per cell >> fp32 eps),
// so the ceil-based runs tile [0, ZB) exactly (pow2 scale => exact floor/ceil
// arithmetic). TS[c] is stored with the same bits as CF[c].x (= horner(cf,0)).
// Total state: 32 KB CF + 8 KB TS + 16 KB map -- all L1-resident in search.
// ---------------------------------------------------------------------------
__global__ void coeff_kernel() {
    int ci = blockIdx.x * blockDim.x + threadIdx.x;
    if (ci >= NC) return;
    const float a0      = g_Ac[1];
    const float a1      = g_Ac[1 + NC];
    const float inv_den = 1.0f / (a1 - a0);
    float P0 = g_Ac[ci];
    float P1 = g_Ac[ci + 1];
    float P2 = g_Ac[ci + 2];
    float P3 = g_Ac[ci + 3];
    float4 cf = make_coeffs(P0, P1, P2, P3, a0, inv_den);
    g_CF[ci] = cf;
    g_TS[ci] = cf.x;                       // T at cell start; cell 0 -> exactly 0.0f
    if (ci == NC - 1) g_TS[NC] = 1.0f;     // T(NFINE) pinned to 1

    // next cell's start value, SAME expression as that cell's cf.x (bit-equal)
    float tnext = (ci == NC - 1) ? 1.0f : (P2 - a0) * inv_den;
    int k0 = (int)ceilf(cf.x  * (float)ZB);
    int k1 = (int)ceilf(tnext * (float)ZB);
    if (k0 < 0) k0 = 0;
    if (k1 > ZB) k1 = ZB;
    for (int k = k0; k < k1; k++) g_map[k] = (unsigned short)ci;
}

// ---------------------------------------------------------------------------
// Kernel 3: per-target inversion with ZERO random L2 traffic. Bucket map
// gives the cell (TS[ci] <= k/ZB <= z); a short advance over the 8 KB TS
// array pins the exact cell (exit => TS[ci+1] > z); then a 9-step
// IN-REGISTER bisection on the cell's cubic (3 FMA/step, bit-identical
// horner) finds lo = max{u : T(ci*512+u) <= z} -- the same semantics as the
// reference 20-step bisection on the fine grid:
// out = (lo_global + 0.5) * 2^-20.
// ---------------------------------------------------------------------------
__device__ __forceinline__ float invert_one(float zi) {
    int k = (int)(zi * (float)ZB);              // exact floor: pow2 scale
    k = min(max(k, 0), ZB - 1);
    int ci = (int)__ldg(&g_map[k]);             // TS[ci] <= k/ZB <= zi
    while (ci < NC - 1 && __ldg(&g_TS[ci + 1]) <= zi) ci++;
    // now TS[ci] <= zi < TS[ci+1] (or ci == NC-1 and zi < TS[NC] = 1)
    float4 cf = __ldg(&g_CF[ci]);
    int lo = 0, hi = 1 << RSH;                  // invariant: T(lo) <= zi < T(hi)
#pragma unroll
    for (int s = 0; s < RSH; s++) {
        int mid = (lo + hi) >> 1;
        if (horner(cf, mid) <= zi) lo = mid; else hi = mid;
    }
    int j = (ci << RSH) + lo;
    return (float)(2 * j + 1) * 0x1p-21f;       // (j + 0.5) * 2^-20, exact
}

__global__ void search_kernel(const float* __restrict__ z, float* __restrict__ out, int n) {
    int i = (blockIdx.x * blockDim.x + threadIdx.x) * 2;
    if (i + 1 < n) {
        float2 zv = *reinterpret_cast<const float2*>(z + i);
        float2 ov;
        ov.x = invert_one(zv.x);
        ov.y = invert_one(zv.y);
        *reinterpret_cast<float2*>(out + i) = ov;
    } else if (i < n) {
        out[i] = invert_one(z[i]);
    }
}

// ---------------------------------------------------------------------------
extern "C" void kernel_launch(void* const* d_in, const int* in_sizes, int n_in,
                              void* d_out, int out_size) {
    const float* z   = (const float*)d_in[0];
    const float* pw1 = (const float*)d_in[1];
    const float* b1  = (const float*)d_in[2];
    const float* pw2 = (const float*)d_in[3];
    const float* b2  = (const float*)d_in[4];
    const float* pw3 = (const float*)d_in[5];
    const float* b3  = (const float*)d_in[6];
    float* out = (float*)d_out;
    int n = in_sizes[0];

    prep_kernel<<<(H * H + 255) / 256, 256>>>(pw1, b1, pw2, b2, pw3, b3);
    coarse_kernel<<<(NCTOT * 32 + 255) / 256, 256>>>();
    coeff_kernel<<<(NC + 255) / 256, 256>>>();
    int nq = (n + 1) / 2;
    search_kernel<<<(nq + 255) / 256, 256>>>(z, out, n);
}